// round 3
// baseline (speedup 1.0000x reference)
#include <cuda_runtime.h>
#include <math_constants.h>

#define NP    16384
#define GRIDD 64
#define NCELL (GRIDD * GRIDD * GRIDD)   // 262144
#define ORG   (-4.5f)
#define WID   (9.0f / GRIDD)            // 0.140625
#define INVW  (GRIDD / 9.0f)

// ---------------- device scratch (static, no allocs) ----------------
__device__ int    g_count[2][NCELL];
__device__ int2   g_meta[2][NCELL];     // (start, count)
__device__ int    g_cursor[2][NCELL];
__device__ float4 g_pts[2][NP];         // cell-sorted points (x,y,z,0)
__device__ float  g_mind2[2 * NP];      // per-query min squared distance

__device__ __forceinline__ int clampi(int v, int lo, int hi) {
    return v < lo ? lo : (v > hi ? hi : v);
}

__device__ __forceinline__ void cell_of(float x, float y, float z,
                                        int& cx, int& cy, int& cz) {
    cx = clampi((int)floorf((x - ORG) * INVW), 0, GRIDD - 1);
    cy = clampi((int)floorf((y - ORG) * INVW), 0, GRIDD - 1);
    cz = clampi((int)floorf((z - ORG) * INVW), 0, GRIDD - 1);
}

// ---------------- kernel 1: zero cell counts ----------------
__global__ void zero_kernel() {
    int i = blockIdx.x * blockDim.x + threadIdx.x;
    if (i < 2 * NCELL) ((int*)g_count)[i] = 0;
}

// ---------------- kernel 2: count points per cell (both clouds) ----------------
__global__ __launch_bounds__(256)
void count_kernel(const float* __restrict__ pred, const float* __restrict__ gt) {
    int i = blockIdx.x * blockDim.x + threadIdx.x;   // [0, 2*NP)
    int cloud = i >> 14;
    int idx = i & (NP - 1);
    const float* r = (cloud ? gt : pred) + (size_t)idx * 6;
    int cx, cy, cz;
    cell_of(r[0], r[1], r[2], cx, cy, cz);
    atomicAdd(&g_count[cloud][(cz * GRIDD + cy) * GRIDD + cx], 1);
}

// ---------------- kernel 3: exclusive scan per cloud (1 block each) ----------------
__global__ __launch_bounds__(1024)
void scan_kernel() {
    const int a = blockIdx.x;        // cloud
    const int t = threadIdx.x;       // 1024 threads, 256 cells each
    const int4* c4 = (const int4*)g_count[a];

    int s = 0;
#pragma unroll 8
    for (int i = 0; i < 64; i++) {
        int4 v = c4[t * 64 + i];
        s += v.x + v.y + v.z + v.w;
    }

    __shared__ int sm[1024];
    sm[t] = s;
    __syncthreads();
    for (int d = 1; d < 1024; d <<= 1) {
        int v = (t >= d) ? sm[t - d] : 0;
        __syncthreads();
        sm[t] += v;
        __syncthreads();
    }
    int run = sm[t] - s;   // exclusive prefix

#pragma unroll 8
    for (int i = 0; i < 256; i++) {
        int c = g_count[a][t * 256 + i];
        g_meta[a][t * 256 + i] = make_int2(run, c);
        g_cursor[a][t * 256 + i] = run;
        run += c;
    }
}

// ---------------- kernel 4: scatter points into cell order ----------------
__global__ __launch_bounds__(256)
void scatter_kernel(const float* __restrict__ pred, const float* __restrict__ gt) {
    int i = blockIdx.x * blockDim.x + threadIdx.x;
    int cloud = i >> 14;
    int idx = i & (NP - 1);
    const float* r = (cloud ? gt : pred) + (size_t)idx * 6;
    float x = r[0], y = r[1], z = r[2];
    int cx, cy, cz;
    cell_of(x, y, z, cx, cy, cz);
    int pos = atomicAdd(&g_cursor[cloud][(cz * GRIDD + cy) * GRIDD + cx], 1);
    g_pts[cloud][pos] = make_float4(x, y, z, 0.0f);
}

// scan a contiguous run of cells [xa..xb] in row (yc,zc) — point ranges are
// x-contiguous by construction of the scan order.
__device__ __forceinline__ void scan_row(int sdb, int zc, int yc, int xa, int xb,
                                         float qx, float qy, float qz, float& best) {
    int base = (zc * GRIDD + yc) * GRIDD;
    int2 m0 = g_meta[sdb][base + xa];
    int2 m1 = g_meta[sdb][base + xb];
    int p = m0.x, e = m1.x + m1.y;
    const float4* __restrict__ pts = g_pts[sdb];
    for (; p < e; p++) {
        float4 g = pts[p];
        float dx = qx - g.x, dy = qy - g.y, dz = qz - g.z;
        float d2 = fmaf(dx, dx, fmaf(dy, dy, dz * dz));
        best = fminf(best, d2);
    }
}

__device__ __forceinline__ void scan_one(int sdb, int zc, int yc, int xc,
                                         float qx, float qy, float qz, float& best) {
    scan_row(sdb, zc, yc, xc, xc, qx, qy, qz, best);
}

// ---------------- kernel 5: exact NN via expanding Chebyshev rings ----------------
__global__ __launch_bounds__(256)
void query_kernel(const float* __restrict__ pred, const float* __restrict__ gt) {
    int i = blockIdx.x * blockDim.x + threadIdx.x;   // [0, 2*NP)
    int dir = i >> 14;                                // 0: pred->gt, 1: gt->pred
    int idx = i & (NP - 1);
    const float* q = (dir ? gt : pred) + (size_t)idx * 6;
    const int sdb = dir ^ 1;                          // structure to search

    float qx = q[0], qy = q[1], qz = q[2];
    int cx, cy, cz;
    cell_of(qx, qy, qz, cx, cy, cz);

    // distances from q to the 6 faces of its (clamped) cell
    float f0 = (cx + 1) * WID + ORG - qx;
    float f1 = qx - (cx * WID + ORG);
    float f2 = (cy + 1) * WID + ORG - qy;
    float f3 = qy - (cy * WID + ORG);
    float f4 = (cz + 1) * WID + ORG - qz;
    float f5 = qz - (cz * WID + ORG);
    float fmin6 = fminf(fminf(fminf(f0, f1), fminf(f2, f3)), fminf(f4, f5));

    float best = CUDART_INF_F;

    // k = 0: own cell
    scan_one(sdb, cz, cy, cx, qx, qy, qz, best);
    if (!(fmin6 > 0.0f && best <= fmin6 * fmin6)) {
        // expanding shells; each cell scanned exactly once at its Chebyshev dist
        for (int k = 1; k < GRIDD; k++) {
            int x0 = max(cx - k, 0), x1 = min(cx + k, GRIDD - 1);
            int y0 = max(cy - k, 0), y1 = min(cy + k, GRIDD - 1);
            int z0 = max(cz - k, 0), z1 = min(cz + k, GRIDD - 1);
            for (int zc = z0; zc <= z1; zc++) {
                bool zshell = (cz - zc == k) || (zc - cz == k);
                for (int yc = y0; yc <= y1; yc++) {
                    bool shellrow = zshell || (cy - yc == k) || (yc - cy == k);
                    if (shellrow) {
                        scan_row(sdb, zc, yc, x0, x1, qx, qy, qz, best);
                    } else {
                        if (cx - k >= 0)        scan_one(sdb, zc, yc, cx - k, qx, qy, qz, best);
                        if (cx + k <= GRIDD - 1) scan_one(sdb, zc, yc, cx + k, qx, qy, qz, best);
                    }
                }
            }
            float bnd = k * WID + fmin6;  // any unscanned point is >= bnd away
            if (bnd > 0.0f && best <= bnd * bnd) break;
        }
    }
    g_mind2[i] = best;
}

// ---------------- kernel 6: fused final reduction (1 block, deterministic) ----------------
__global__ __launch_bounds__(1024)
void reduce_kernel(const float* __restrict__ pred, const float* __restrict__ gt,
                   float* __restrict__ out) {
    const int t = threadIdx.x;

    float sd = 0.0f;
#pragma unroll
    for (int j = 0; j < 32; j++)
        sd += sqrtf(fmaxf(g_mind2[t + j * 1024], 0.0f));

    float sc = 0.0f;
#pragma unroll
    for (int j = 0; j < 48; j++) {
        int ce = t + j * 1024;          // [0, 49152)
        int i = ce / 3, c = ce - 3 * i;
        sc += fabsf(pred[(size_t)i * 6 + 3 + c] - gt[(size_t)i * 6 + 3 + c]);
    }

    __shared__ float s1[1024];
    __shared__ float s2[1024];
    s1[t] = sd;
    s2[t] = sc;
    __syncthreads();
#pragma unroll
    for (int s = 512; s > 0; s >>= 1) {
        if (t < s) { s1[t] += s1[t + s]; s2[t] += s2[t + s]; }
        __syncthreads();
    }
    if (t == 0) {
        // chamfer = (sum_fwd + sum_bwd)/NP ; color = mean L1 over NP*3
        out[0] = s1[0] * (1.0f / (float)NP) + 0.1f * s2[0] * (1.0f / (float)(NP * 3));
    }
}

extern "C" void kernel_launch(void* const* d_in, const int* in_sizes, int n_in,
                              void* d_out, int out_size) {
    const float* pred = (const float*)d_in[0];
    const float* gt   = (const float*)d_in[1];
    float* out        = (float*)d_out;
    (void)in_sizes; (void)n_in; (void)out_size;

    zero_kernel<<<(2 * NCELL + 1023) / 1024, 1024>>>();
    count_kernel<<<(2 * NP) / 256, 256>>>(pred, gt);
    scan_kernel<<<2, 1024>>>();
    scatter_kernel<<<(2 * NP) / 256, 256>>>(pred, gt);
    query_kernel<<<(2 * NP) / 256, 256>>>(pred, gt);
    reduce_kernel<<<1, 1024>>>(pred, gt, out);
}

// round 4
// speedup vs baseline: 5.5584x; 5.5584x over previous
#include <cuda_runtime.h>
#include <math_constants.h>

#define NP    16384
#define GRIDD 32
#define NCELL (GRIDD * GRIDD * GRIDD)   // 32768
#define ORG   (-4.5f)
#define WID   (9.0f / GRIDD)            // 0.28125
#define INVW  (GRIDD / 9.0f)

// ---------------- device scratch (static, no allocs) ----------------
__device__ int    g_count[2][NCELL];
__device__ int2   g_meta[2][NCELL];     // (start, count)
__device__ int    g_cursor[2][NCELL];
__device__ float4 g_pts[2][NP];         // cell-sorted points
__device__ float  g_mind2[2 * NP];      // per-query min squared distance

__device__ __forceinline__ int clampi(int v, int lo, int hi) {
    return v < lo ? lo : (v > hi ? hi : v);
}
__device__ __forceinline__ void cell_of(float x, float y, float z,
                                        int& cx, int& cy, int& cz) {
    cx = clampi((int)floorf((x - ORG) * INVW), 0, GRIDD - 1);
    cy = clampi((int)floorf((y - ORG) * INVW), 0, GRIDD - 1);
    cz = clampi((int)floorf((z - ORG) * INVW), 0, GRIDD - 1);
}

// ---------------- kernel 1: zero cell counts ----------------
__global__ void zero_kernel() {
    int i = blockIdx.x * blockDim.x + threadIdx.x;
    if (i < 2 * NCELL) ((int*)g_count)[i] = 0;
}

// ---------------- kernel 2: count points per cell ----------------
__global__ __launch_bounds__(256)
void count_kernel(const float* __restrict__ pred, const float* __restrict__ gt) {
    int i = blockIdx.x * blockDim.x + threadIdx.x;   // [0, 2*NP)
    int cloud = i >> 14;
    int idx = i & (NP - 1);
    const float* r = (cloud ? gt : pred) + (size_t)idx * 6;
    int cx, cy, cz;
    cell_of(r[0], r[1], r[2], cx, cy, cz);
    atomicAdd(&g_count[cloud][(cz * GRIDD + cy) * GRIDD + cx], 1);
}

// ---------------- kernel 3: exclusive scan per cloud (1 block each) ----------------
__global__ __launch_bounds__(1024)
void scan_kernel() {
    const int a = blockIdx.x;        // cloud
    const int t = threadIdx.x;       // 1024 threads x 32 cells
    const int4* c4 = (const int4*)g_count[a];

    int s = 0;
#pragma unroll
    for (int i = 0; i < 8; i++) {
        int4 v = c4[t * 8 + i];
        s += v.x + v.y + v.z + v.w;
    }

    __shared__ int sm[1024];
    sm[t] = s;
    __syncthreads();
    for (int d = 1; d < 1024; d <<= 1) {
        int v = (t >= d) ? sm[t - d] : 0;
        __syncthreads();
        sm[t] += v;
        __syncthreads();
    }
    int run = sm[t] - s;   // exclusive prefix

#pragma unroll
    for (int i = 0; i < 32; i++) {
        int c = g_count[a][t * 32 + i];
        g_meta[a][t * 32 + i] = make_int2(run, c);
        g_cursor[a][t * 32 + i] = run;
        run += c;
    }
}

// ---------------- kernel 4: scatter points into cell order ----------------
__global__ __launch_bounds__(256)
void scatter_kernel(const float* __restrict__ pred, const float* __restrict__ gt) {
    int i = blockIdx.x * blockDim.x + threadIdx.x;
    int cloud = i >> 14;
    int idx = i & (NP - 1);
    const float* r = (cloud ? gt : pred) + (size_t)idx * 6;
    float x = r[0], y = r[1], z = r[2];
    int cx, cy, cz;
    cell_of(x, y, z, cx, cy, cz);
    int pos = atomicAdd(&g_cursor[cloud][(cz * GRIDD + cy) * GRIDD + cx], 1);
    g_pts[cloud][pos] = make_float4(x, y, z, 0.0f);
}

// warp-cooperative scan of contiguous cell run [c0..c1] (points x-contiguous)
__device__ __forceinline__ void scan_rng(int sdb, int c0, int c1, int lane,
                                         float qx, float qy, float qz, float& best) {
    int2 m0 = g_meta[sdb][c0];          // broadcast LDG (all lanes same addr)
    int2 m1 = g_meta[sdb][c1];
    int e = m1.x + m1.y;
    const float4* __restrict__ pts = g_pts[sdb];
    for (int p = m0.x + lane; p < e; p += 32) {
        float4 g = pts[p];
        float dx = qx - g.x, dy = qy - g.y, dz = qz - g.z;
        float d2 = fmaf(dx, dx, fmaf(dy, dy, dz * dz));
        best = fminf(best, d2);
    }
}

// ---------------- kernel 5: exact NN, one WARP per query ----------------
__global__ __launch_bounds__(256)
void query_kernel(const float* __restrict__ pred, const float* __restrict__ gt) {
    const int gw   = (blockIdx.x * blockDim.x + threadIdx.x) >> 5;  // [0, 2*NP)
    const int lane = threadIdx.x & 31;
    const int dir  = gw >> 14;
    const int idx  = gw & (NP - 1);
    const float* q = (dir ? gt : pred) + (size_t)idx * 6;
    const int sdb  = dir ^ 1;

    float qx = q[0], qy = q[1], qz = q[2];   // broadcast loads
    int cx, cy, cz;
    cell_of(qx, qy, qz, cx, cy, cz);

    // face distances; grid-edge faces -> +INF (no cells beyond them)
    float f0 = (cx == GRIDD - 1) ? CUDART_INF_F : (cx + 1) * WID + ORG - qx;
    float f1 = (cx == 0)         ? CUDART_INF_F : qx - (cx * WID + ORG);
    float f2 = (cy == GRIDD - 1) ? CUDART_INF_F : (cy + 1) * WID + ORG - qy;
    float f3 = (cy == 0)         ? CUDART_INF_F : qy - (cy * WID + ORG);
    float f4 = (cz == GRIDD - 1) ? CUDART_INF_F : (cz + 1) * WID + ORG - qz;
    float f5 = (cz == 0)         ? CUDART_INF_F : qz - (cz * WID + ORG);
    float fmin6 = fminf(fminf(fminf(f0, f1), fminf(f2, f3)), fminf(f4, f5));

    float best = CUDART_INF_F;

    for (int k = 0; k < GRIDD; k++) {
        int x0 = max(cx - k, 0), x1 = min(cx + k, GRIDD - 1);
        int y0 = max(cy - k, 0), y1 = min(cy + k, GRIDD - 1);
        int z0 = max(cz - k, 0), z1 = min(cz + k, GRIDD - 1);
        for (int zc = z0; zc <= z1; zc++) {
            bool zsh = (zc == cz - k) || (zc == cz + k);
            for (int yc = y0; yc <= y1; yc++) {
                int base = (zc * GRIDD + yc) * GRIDD;
                if (zsh || (yc == cy - k) || (yc == cy + k)) {
                    scan_rng(sdb, base + x0, base + x1, lane, qx, qy, qz, best);
                } else {
                    if (cx - k >= 0)
                        scan_rng(sdb, base + cx - k, base + cx - k, lane, qx, qy, qz, best);
                    if (cx + k <= GRIDD - 1)
                        scan_rng(sdb, base + cx + k, base + cx + k, lane, qx, qy, qz, best);
                }
            }
        }
        // warp-wide min, uniform termination test
        float bm = best;
#pragma unroll
        for (int s = 16; s > 0; s >>= 1)
            bm = fminf(bm, __shfl_xor_sync(0xffffffffu, bm, s));
        float bnd = k * WID + fmin6;    // any unscanned point is >= bnd away
        if (bnd > 0.0f && bm <= bnd * bnd) { best = bm; break; }
        best = bm;                       // keep reduced value (harmless)
    }

    if (lane == 0) g_mind2[gw] = best;
}

// ---------------- kernel 6: fused final reduction (1 block, deterministic) ----------------
__global__ __launch_bounds__(1024)
void reduce_kernel(const float* __restrict__ pred, const float* __restrict__ gt,
                   float* __restrict__ out) {
    const int t = threadIdx.x;

    float sd = 0.0f;
#pragma unroll
    for (int j = 0; j < 32; j++)
        sd += sqrtf(fmaxf(g_mind2[t + j * 1024], 0.0f));

    float sc = 0.0f;
#pragma unroll
    for (int j = 0; j < 48; j++) {
        int ce = t + j * 1024;          // [0, 49152)
        int i = ce / 3, c = ce - 3 * i;
        sc += fabsf(pred[(size_t)i * 6 + 3 + c] - gt[(size_t)i * 6 + 3 + c]);
    }

    __shared__ float s1[1024];
    __shared__ float s2[1024];
    s1[t] = sd;
    s2[t] = sc;
    __syncthreads();
#pragma unroll
    for (int s = 512; s > 0; s >>= 1) {
        if (t < s) { s1[t] += s1[t + s]; s2[t] += s2[t + s]; }
        __syncthreads();
    }
    if (t == 0) {
        out[0] = s1[0] * (1.0f / (float)NP) + 0.1f * s2[0] * (1.0f / (float)(NP * 3));
    }
}

extern "C" void kernel_launch(void* const* d_in, const int* in_sizes, int n_in,
                              void* d_out, int out_size) {
    const float* pred = (const float*)d_in[0];
    const float* gt   = (const float*)d_in[1];
    float* out        = (float*)d_out;
    (void)in_sizes; (void)n_in; (void)out_size;

    zero_kernel<<<(2 * NCELL + 1023) / 1024, 1024>>>();
    count_kernel<<<(2 * NP) / 256, 256>>>(pred, gt);
    scan_kernel<<<2, 1024>>>();
    scatter_kernel<<<(2 * NP) / 256, 256>>>(pred, gt);
    query_kernel<<<(2 * NP * 32) / 256, 256>>>(pred, gt);
    reduce_kernel<<<1, 1024>>>(pred, gt, out);
}

// round 5
// speedup vs baseline: 6.6584x; 1.1979x over previous
#include <cuda_runtime.h>
#include <math_constants.h>

#define NP    16384
#define GRIDD 32
#define NCELL (GRIDD * GRIDD * GRIDD)   // 32768
#define ORG   (-4.5f)
#define WID   (9.0f / GRIDD)            // 0.28125
#define INVW  (GRIDD / 9.0f)
#define FULLM 0xffffffffu
#define FXS   268435456.0f              // 2^28 fixed-point scale

// ---------------- device scratch (static, no allocs) ----------------
__device__ int    g_count[2][NCELL];
__device__ int2   g_meta[2][NCELL];     // (start, count)
__device__ int    g_cursor[2][NCELL];
__device__ float4 g_pts[2][NP];         // cell-sorted points
__device__ float  g_mind2[2 * NP];      // per-query min squared distance

__device__ __forceinline__ int clampi(int v, int lo, int hi) {
    return v < lo ? lo : (v > hi ? hi : v);
}
__device__ __forceinline__ void cell_of(float x, float y, float z,
                                        int& cx, int& cy, int& cz) {
    cx = clampi((int)floorf((x - ORG) * INVW), 0, GRIDD - 1);
    cy = clampi((int)floorf((y - ORG) * INVW), 0, GRIDD - 1);
    cz = clampi((int)floorf((z - ORG) * INVW), 0, GRIDD - 1);
}

// ---------------- kernel 1: zero cell counts ----------------
__global__ void zero_kernel() {
    int i = blockIdx.x * blockDim.x + threadIdx.x;
    if (i < 2 * NCELL) ((int*)g_count)[i] = 0;
}

// ---------------- kernel 2: count points per cell ----------------
__global__ __launch_bounds__(256)
void count_kernel(const float* __restrict__ pred, const float* __restrict__ gt) {
    int i = blockIdx.x * blockDim.x + threadIdx.x;   // [0, 2*NP)
    int cloud = i >> 14;
    int idx = i & (NP - 1);
    const float* r = (cloud ? gt : pred) + (size_t)idx * 6;
    int cx, cy, cz;
    cell_of(r[0], r[1], r[2], cx, cy, cz);
    atomicAdd(&g_count[cloud][(cz * GRIDD + cy) * GRIDD + cx], 1);
}

// ---------------- kernel 3: exclusive scan per cloud (1 block each) ----------------
__global__ __launch_bounds__(1024)
void scan_kernel() {
    const int a = blockIdx.x;        // cloud
    const int t = threadIdx.x;       // 1024 threads x 32 cells
    const int lane = t & 31, w = t >> 5;
    const int4* c4 = (const int4*)g_count[a];

    int s = 0;
#pragma unroll
    for (int i = 0; i < 8; i++) {
        int4 v = c4[t * 8 + i];
        s += v.x + v.y + v.z + v.w;
    }
    int si = s;
#pragma unroll
    for (int d = 1; d < 32; d <<= 1) {
        int v = __shfl_up_sync(FULLM, si, d);
        if (lane >= d) si += v;
    }
    __shared__ int ws[32];
    if (lane == 31) ws[w] = si;
    __syncthreads();
    if (w == 0) {
        int v = ws[lane];
        int vi = v;
#pragma unroll
        for (int d = 1; d < 32; d <<= 1) {
            int x = __shfl_up_sync(FULLM, vi, d);
            if (lane >= d) vi += x;
        }
        ws[lane] = vi - v;   // exclusive warp offsets
    }
    __syncthreads();
    int run = ws[w] + si - s;   // exclusive prefix for this thread's 32 cells

#pragma unroll
    for (int i = 0; i < 32; i++) {
        int c = g_count[a][t * 32 + i];
        g_meta[a][t * 32 + i] = make_int2(run, c);
        g_cursor[a][t * 32 + i] = run;
        run += c;
    }
}

// ---------------- kernel 4: scatter points into cell order ----------------
__global__ __launch_bounds__(256)
void scatter_kernel(const float* __restrict__ pred, const float* __restrict__ gt) {
    int i = blockIdx.x * blockDim.x + threadIdx.x;
    int cloud = i >> 14;
    int idx = i & (NP - 1);
    const float* r = (cloud ? gt : pred) + (size_t)idx * 6;
    float x = r[0], y = r[1], z = r[2];
    int cx, cy, cz;
    cell_of(x, y, z, cx, cy, cz);
    int pos = atomicAdd(&g_cursor[cloud][(cz * GRIDD + cy) * GRIDD + cx], 1);
    g_pts[cloud][pos] = make_float4(x, y, z, 0.0f);
}

// ---------------- kernel 5: exact NN, one WARP per query ----------------
// Queries taken from the CELL-SORTED array (locality; multiset of mins is
// permutation-invariant). Phase 1 scans the 3x3x3 box as one flattened
// lane-strided stream (single meta round trip). Rare fallback: doubling boxes.
__global__ __launch_bounds__(256)
void query_kernel() {
    const int lane = threadIdx.x & 31;
    const int gw   = (blockIdx.x * blockDim.x + threadIdx.x) >> 5;  // [0, 2*NP)
    const int dir  = gw >> 14;
    const int idx  = gw & (NP - 1);
    const int sdb  = dir ^ 1;

    float4 qp = g_pts[dir][idx];
    float qx = qp.x, qy = qp.y, qz = qp.z;
    int cx, cy, cz;
    cell_of(qx, qy, qz, cx, cy, cz);

    // face distances; grid-edge faces -> +INF (no cells beyond them)
    float f0 = (cx == GRIDD - 1) ? CUDART_INF_F : (cx + 1) * WID + ORG - qx;
    float f1 = (cx == 0)         ? CUDART_INF_F : qx - (cx * WID + ORG);
    float f2 = (cy == GRIDD - 1) ? CUDART_INF_F : (cy + 1) * WID + ORG - qy;
    float f3 = (cy == 0)         ? CUDART_INF_F : qy - (cy * WID + ORG);
    float f4 = (cz == GRIDD - 1) ? CUDART_INF_F : (cz + 1) * WID + ORG - qz;
    float f5 = (cz == 0)         ? CUDART_INF_F : qz - (cz * WID + ORG);
    float fmin6 = fminf(fminf(fminf(f0, f1), fminf(f2, f3)), fminf(f4, f5));

    const float4* __restrict__ pts  = g_pts[sdb];
    const int2*   __restrict__ meta = g_meta[sdb];

    float best = CUDART_INF_F;

    // -------- phase 1: flattened 3x3x3 box --------
    {
        int x0 = max(cx - 1, 0), x1 = min(cx + 1, GRIDD - 1);
        int s = 0, c = 0;
        if (lane < 9) {
            int zc = cz + lane / 3 - 1;
            int yc = cy + (lane % 3) - 1;
            if (zc >= 0 && zc < GRIDD && yc >= 0 && yc < GRIDD) {
                int base = (zc * GRIDD + yc) * GRIDD;
                int2 m0 = meta[base + x0];
                int2 m1 = meta[base + x1];
                s = m0.x;
                c = m1.x + m1.y - m0.x;
            }
        }
        int p = c;
#pragma unroll
        for (int d = 1; d < 16; d <<= 1) {
            int v = __shfl_up_sync(FULLM, p, d);
            if (lane >= d) p += v;
        }
        int E  = __shfl_sync(FULLM, p, 8);   // total candidates
        int pe = p - c;                       // exclusive prefix of this row
        int P[9], S[9];
#pragma unroll
        for (int r = 0; r < 9; r++) {
            P[r] = __shfl_sync(FULLM, pe, r);
            S[r] = __shfl_sync(FULLM, s,  r);
        }
        for (int i = lane; i < E; i += 32) {
            int addr = S[0] + i;
#pragma unroll
            for (int r = 1; r < 9; r++)
                if (i >= P[r]) addr = S[r] + (i - P[r]);
            float4 g = pts[addr];
            float dx = qx - g.x, dy = qy - g.y, dz = qz - g.z;
            best = fminf(best, fmaf(dx, dx, fmaf(dy, dy, dz * dz)));
        }
    }
#pragma unroll
    for (int sft = 16; sft > 0; sft >>= 1)
        best = fminf(best, __shfl_xor_sync(FULLM, best, sft));

    float bnd = WID + fmin6;   // unscanned points are >= bnd away
    if (!(best <= bnd * bnd)) {
        // -------- rare fallback: doubling boxes (rescans are cheap in sparse tails) --------
        for (int kk = 3;; kk = 2 * kk + 1) {
            if (kk > GRIDD - 1) kk = GRIDD - 1;
            int W = 2 * kk + 1;
            int nrows = W * W;
            int x0 = max(cx - kk, 0), x1 = min(cx + kk, GRIDD - 1);
            for (int rb = 0; rb < nrows; rb += 32) {
                int rr = rb + lane;
                int s = 0, e = 0;
                if (rr < nrows) {
                    int zc = cz + rr / W - kk;
                    int yc = cy + rr % W - kk;
                    if (zc >= 0 && zc < GRIDD && yc >= 0 && yc < GRIDD) {
                        int base = (zc * GRIDD + yc) * GRIDD;
                        int2 m0 = meta[base + x0];
                        int2 m1 = meta[base + x1];
                        s = m0.x;
                        e = m1.x + m1.y;
                    }
                }
                int nr = min(32, nrows - rb);
                for (int r = 0; r < nr; r++) {
                    int ss = __shfl_sync(FULLM, s, r);
                    int ee = __shfl_sync(FULLM, e, r);
                    for (int pp = ss + lane; pp < ee; pp += 32) {
                        float4 g = pts[pp];
                        float dx = qx - g.x, dy = qy - g.y, dz = qz - g.z;
                        best = fminf(best, fmaf(dx, dx, fmaf(dy, dy, dz * dz)));
                    }
                }
            }
#pragma unroll
            for (int sft = 16; sft > 0; sft >>= 1)
                best = fminf(best, __shfl_xor_sync(FULLM, best, sft));
            if (kk == GRIDD - 1) break;           // whole grid scanned -> exact
            float b2 = kk * WID + fmin6;
            if (best <= b2 * b2) break;
        }
    }

    if (lane == 0) g_mind2[gw] = fmaxf(best, 0.0f);
}

// ---------------- kernel 6: fused final reduction ----------------
// Distance sum in int64 fixed point (2^-28): integer addition is
// permutation-invariant -> bit-deterministic despite race-ordered scatter.
__global__ __launch_bounds__(1024)
void reduce_kernel(const float* __restrict__ pred, const float* __restrict__ gt,
                   float* __restrict__ out) {
    const int t = threadIdx.x;

    long long sd = 0;
#pragma unroll
    for (int j = 0; j < 32; j++)
        sd += (long long)llrintf(sqrtf(g_mind2[t + j * 1024]) * FXS);

    float sc = 0.0f;
#pragma unroll
    for (int j = 0; j < 48; j++) {
        int ce = t + j * 1024;          // [0, 49152)
        int i = ce / 3, c = ce - 3 * i;
        sc += fabsf(pred[(size_t)i * 6 + 3 + c] - gt[(size_t)i * 6 + 3 + c]);
    }

    __shared__ long long s1[1024];
    __shared__ float s2[1024];
    s1[t] = sd;
    s2[t] = sc;
    __syncthreads();
#pragma unroll
    for (int s = 512; s > 0; s >>= 1) {
        if (t < s) { s1[t] += s1[t + s]; s2[t] += s2[t + s]; }
        __syncthreads();
    }
    if (t == 0) {
        double dist_sum = (double)s1[0] * (1.0 / (double)FXS);
        out[0] = (float)(dist_sum / (double)NP) + 0.1f * s2[0] * (1.0f / (float)(NP * 3));
    }
}

extern "C" void kernel_launch(void* const* d_in, const int* in_sizes, int n_in,
                              void* d_out, int out_size) {
    const float* pred = (const float*)d_in[0];
    const float* gt   = (const float*)d_in[1];
    float* out        = (float*)d_out;
    (void)in_sizes; (void)n_in; (void)out_size;

    zero_kernel<<<(2 * NCELL + 1023) / 1024, 1024>>>();
    count_kernel<<<(2 * NP) / 256, 256>>>(pred, gt);
    scan_kernel<<<2, 1024>>>();
    scatter_kernel<<<(2 * NP) / 256, 256>>>(pred, gt);
    query_kernel<<<(2 * NP * 32) / 256, 256>>>();
    reduce_kernel<<<1, 1024>>>(pred, gt, out);
}

// round 6
// speedup vs baseline: 8.4987x; 1.2764x over previous
#include <cuda_runtime.h>
#include <math_constants.h>

#define NP    16384
#define GRIDD 32
#define NCELL (GRIDD * GRIDD * GRIDD)   // 32768
#define ORG   (-4.5f)
#define WID   (9.0f / GRIDD)            // 0.28125
#define INVW  (GRIDD / 9.0f)
#define FULLM 0xffffffffu
#define FXS   268435456.0f              // 2^28 fixed-point scale

// ---------------- device scratch (static, no allocs) ----------------
__device__ int    g_count[2][NCELL];
__device__ int2   g_meta[2][NCELL];     // (start, count)
__device__ int    g_cursor[2][NCELL];
__device__ float4 g_pts[2][NP];         // cell-sorted points
__device__ float  g_mind2[2 * NP];      // per-query min squared distance

__device__ __forceinline__ int clampi(int v, int lo, int hi) {
    return v < lo ? lo : (v > hi ? hi : v);
}
__device__ __forceinline__ void cell_of(float x, float y, float z,
                                        int& cx, int& cy, int& cz) {
    cx = clampi((int)floorf((x - ORG) * INVW), 0, GRIDD - 1);
    cy = clampi((int)floorf((y - ORG) * INVW), 0, GRIDD - 1);
    cz = clampi((int)floorf((z - ORG) * INVW), 0, GRIDD - 1);
}

// ---------------- kernel 1: zero cell counts ----------------
__global__ void zero_kernel() {
    int i = blockIdx.x * blockDim.x + threadIdx.x;
    if (i < 2 * NCELL) ((int*)g_count)[i] = 0;
}

// ---------------- kernel 2: count points per cell ----------------
__global__ __launch_bounds__(256)
void count_kernel(const float* __restrict__ pred, const float* __restrict__ gt) {
    int i = blockIdx.x * blockDim.x + threadIdx.x;   // [0, 2*NP)
    int cloud = i >> 14;
    int idx = i & (NP - 1);
    const float* r = (cloud ? gt : pred) + (size_t)idx * 6;
    int cx, cy, cz;
    cell_of(r[0], r[1], r[2], cx, cy, cz);
    atomicAdd(&g_count[cloud][(cz * GRIDD + cy) * GRIDD + cx], 1);
}

// ---------------- kernel 3: exclusive scan per cloud (1 block each) ----------------
__global__ __launch_bounds__(1024)
void scan_kernel() {
    const int a = blockIdx.x;        // cloud
    const int t = threadIdx.x;       // 1024 threads x 32 cells
    const int lane = t & 31, w = t >> 5;
    const int4* c4 = (const int4*)g_count[a];

    int s = 0;
#pragma unroll
    for (int i = 0; i < 8; i++) {
        int4 v = c4[t * 8 + i];
        s += v.x + v.y + v.z + v.w;
    }
    int si = s;
#pragma unroll
    for (int d = 1; d < 32; d <<= 1) {
        int v = __shfl_up_sync(FULLM, si, d);
        if (lane >= d) si += v;
    }
    __shared__ int ws[32];
    if (lane == 31) ws[w] = si;
    __syncthreads();
    if (w == 0) {
        int v = ws[lane];
        int vi = v;
#pragma unroll
        for (int d = 1; d < 32; d <<= 1) {
            int x = __shfl_up_sync(FULLM, vi, d);
            if (lane >= d) vi += x;
        }
        ws[lane] = vi - v;   // exclusive warp offsets
    }
    __syncthreads();
    int run = ws[w] + si - s;   // exclusive prefix for this thread's 32 cells

#pragma unroll
    for (int i = 0; i < 32; i++) {
        int c = g_count[a][t * 32 + i];
        g_meta[a][t * 32 + i] = make_int2(run, c);
        g_cursor[a][t * 32 + i] = run;
        run += c;
    }
}

// ---------------- kernel 4: scatter points into cell order ----------------
__global__ __launch_bounds__(256)
void scatter_kernel(const float* __restrict__ pred, const float* __restrict__ gt) {
    int i = blockIdx.x * blockDim.x + threadIdx.x;
    int cloud = i >> 14;
    int idx = i & (NP - 1);
    const float* r = (cloud ? gt : pred) + (size_t)idx * 6;
    float x = r[0], y = r[1], z = r[2];
    int cx, cy, cz;
    cell_of(x, y, z, cx, cy, cz);
    int pos = atomicAdd(&g_cursor[cloud][(cz * GRIDD + cy) * GRIDD + cx], 1);
    g_pts[cloud][pos] = make_float4(x, y, z, 0.0f);
}

// ---------------- kernel 5: exact NN, one WARP per query ----------------
__global__ __launch_bounds__(256)
void query_kernel() {
    const int lane = threadIdx.x & 31;
    const int gw   = (blockIdx.x * blockDim.x + threadIdx.x) >> 5;  // [0, 2*NP)
    const int dir  = gw >> 14;
    const int idx  = gw & (NP - 1);
    const int sdb  = dir ^ 1;

    float4 qp = g_pts[dir][idx];
    float qx = qp.x, qy = qp.y, qz = qp.z;
    int cx, cy, cz;
    cell_of(qx, qy, qz, cx, cy, cz);

    // face distances; grid-edge faces -> +INF (no cells beyond them)
    float f0 = (cx == GRIDD - 1) ? CUDART_INF_F : (cx + 1) * WID + ORG - qx;
    float f1 = (cx == 0)         ? CUDART_INF_F : qx - (cx * WID + ORG);
    float f2 = (cy == GRIDD - 1) ? CUDART_INF_F : (cy + 1) * WID + ORG - qy;
    float f3 = (cy == 0)         ? CUDART_INF_F : qy - (cy * WID + ORG);
    float f4 = (cz == GRIDD - 1) ? CUDART_INF_F : (cz + 1) * WID + ORG - qz;
    float f5 = (cz == 0)         ? CUDART_INF_F : qz - (cz * WID + ORG);
    float fmin6 = fminf(fminf(fminf(f0, f1), fminf(f2, f3)), fminf(f4, f5));

    const float4* __restrict__ pts  = g_pts[sdb];
    const int2*   __restrict__ meta = g_meta[sdb];

    float best = CUDART_INF_F;

    // -------- phase 1: flattened 3x3x3 box, single meta round-trip --------
    {
        int x0 = max(cx - 1, 0), x1 = min(cx + 1, GRIDD - 1);
        int s = 0, c = 0;
        if (lane < 9) {
            int zc = cz + lane / 3 - 1;
            int yc = cy + (lane % 3) - 1;
            if (zc >= 0 && zc < GRIDD && yc >= 0 && yc < GRIDD) {
                int base = (zc * GRIDD + yc) * GRIDD;
                int2 m0 = meta[base + x0];
                int2 m1 = meta[base + x1];
                s = m0.x;
                c = m1.x + m1.y - m0.x;
            }
        }
        int p = c;
#pragma unroll
        for (int d = 1; d < 16; d <<= 1) {
            int v = __shfl_up_sync(FULLM, p, d);
            if (lane >= d) p += v;
        }
        int E  = __shfl_sync(FULLM, p, 8);   // total candidates
        int pe = p - c;                       // exclusive prefix of this row
        int P[9], S[9];
#pragma unroll
        for (int r = 0; r < 9; r++) {
            P[r] = __shfl_sync(FULLM, pe, r);
            S[r] = __shfl_sync(FULLM, s,  r);
        }
        for (int i = lane; i < E; i += 32) {
            int addr = S[0] + i;
#pragma unroll
            for (int r = 1; r < 9; r++)
                if (i >= P[r]) addr = S[r] + (i - P[r]);
            float4 g = pts[addr];
            float dx = qx - g.x, dy = qy - g.y, dz = qz - g.z;
            best = fminf(best, fmaf(dx, dx, fmaf(dy, dy, dz * dz)));
        }
    }
#pragma unroll
    for (int sft = 16; sft > 0; sft >>= 1)
        best = fminf(best, __shfl_xor_sync(FULLM, best, sft));

    float bnd = WID + fmin6;   // unscanned points are >= bnd away
    if (!(best <= bnd * bnd)) {
        // -------- fallback: direct-jump box scan with ballot-skip of empty rows --------
        int kk;
        if (best < CUDART_INF_F) {
            kk = (int)ceilf((sqrtf(best) - fmin6) * (1.0f / WID));
            kk = clampi(kk, 2, GRIDD - 1);
        } else {
            kk = 3;
        }
        for (;;) {
            const int W = 2 * kk + 1;
            const int nrows = W * W;
            const int x0 = max(cx - kk, 0), x1 = min(cx + kk, GRIDD - 1);
            for (int rb = 0; rb < nrows; rb += 32) {
                int rr = rb + lane;
                int s = 0, e = 0;
                if (rr < nrows) {
                    int zc = cz + rr / W - kk;
                    int yc = cy + rr % W - kk;
                    if ((unsigned)zc < GRIDD && (unsigned)yc < GRIDD) {
                        int base = (zc * GRIDD + yc) * GRIDD;
                        int2 m0 = meta[base + x0];
                        int2 m1 = meta[base + x1];
                        s = m0.x;
                        e = m1.x + m1.y;
                    }
                }
                unsigned nz = __ballot_sync(FULLM, e > s);   // skip empty rows
                while (nz) {
                    int r = __ffs(nz) - 1;
                    nz &= nz - 1;
                    int ss = __shfl_sync(FULLM, s, r);
                    int ee = __shfl_sync(FULLM, e, r);
                    for (int pp = ss + lane; pp < ee; pp += 32) {
                        float4 g = pts[pp];
                        float dx = qx - g.x, dy = qy - g.y, dz = qz - g.z;
                        best = fminf(best, fmaf(dx, dx, fmaf(dy, dy, dz * dz)));
                    }
                }
            }
#pragma unroll
            for (int sft = 16; sft > 0; sft >>= 1)
                best = fminf(best, __shfl_xor_sync(FULLM, best, sft));
            if (kk == GRIDD - 1) break;           // whole grid scanned -> exact
            float b2 = kk * WID + fmin6;
            if (best <= b2 * b2) break;           // bound met -> exact
            int nk;
            if (best < CUDART_INF_F)
                nk = (int)ceilf((sqrtf(best) - fmin6) * (1.0f / WID));
            else
                nk = 2 * kk + 1;
            if (nk <= kk) nk = kk + 1;
            kk = min(nk, GRIDD - 1);
        }
    }

    if (lane == 0) g_mind2[gw] = fmaxf(best, 0.0f);
}

// ---------------- kernel 6: fused final reduction ----------------
// Distance sum in int64 fixed point (2^-28): integer addition is
// permutation-invariant -> bit-deterministic despite race-ordered scatter.
__global__ __launch_bounds__(1024)
void reduce_kernel(const float* __restrict__ pred, const float* __restrict__ gt,
                   float* __restrict__ out) {
    const int t = threadIdx.x;

    long long sd = 0;
#pragma unroll
    for (int j = 0; j < 32; j++)
        sd += (long long)llrintf(sqrtf(g_mind2[t + j * 1024]) * FXS);

    float sc = 0.0f;
#pragma unroll
    for (int j = 0; j < 48; j++) {
        int ce = t + j * 1024;          // [0, 49152)
        int i = ce / 3, c = ce - 3 * i;
        sc += fabsf(pred[(size_t)i * 6 + 3 + c] - gt[(size_t)i * 6 + 3 + c]);
    }

    __shared__ long long s1[1024];
    __shared__ float s2[1024];
    s1[t] = sd;
    s2[t] = sc;
    __syncthreads();
#pragma unroll
    for (int s = 512; s > 0; s >>= 1) {
        if (t < s) { s1[t] += s1[t + s]; s2[t] += s2[t + s]; }
        __syncthreads();
    }
    if (t == 0) {
        double dist_sum = (double)s1[0] * (1.0 / (double)FXS);
        out[0] = (float)(dist_sum / (double)NP) + 0.1f * s2[0] * (1.0f / (float)(NP * 3));
    }
}

extern "C" void kernel_launch(void* const* d_in, const int* in_sizes, int n_in,
                              void* d_out, int out_size) {
    const float* pred = (const float*)d_in[0];
    const float* gt   = (const float*)d_in[1];
    float* out        = (float*)d_out;
    (void)in_sizes; (void)n_in; (void)out_size;

    zero_kernel<<<(2 * NCELL + 1023) / 1024, 1024>>>();
    count_kernel<<<(2 * NP) / 256, 256>>>(pred, gt);
    scan_kernel<<<2, 1024>>>();
    scatter_kernel<<<(2 * NP) / 256, 256>>>(pred, gt);
    query_kernel<<<(2 * NP * 32) / 256, 256>>>();
    reduce_kernel<<<1, 1024>>>(pred, gt, out);
}